// round 9
// baseline (speedup 1.0000x reference)
#include <cuda_runtime.h>
#include <cstdint>

#define BB 1024
#define SS 512
#define TT 64

// ---------------- device scratch ----------------
__device__ double g_ll[BB];
__device__ unsigned int g_ctr = 0;

// ---------------- helpers ----------------
__device__ __forceinline__ unsigned int hfma2_bf(unsigned int a, unsigned int b, unsigned int c) {
    unsigned int d;
    asm("fma.rn.bf16x2 %0, %1, %2, %3;" : "=r"(d) : "r"(a), "r"(b), "r"(c));
    return d;
}
__device__ __forceinline__ unsigned int hadd2_bf(unsigned int a, unsigned int b) {
    unsigned int d;
    asm("add.rn.bf16x2 %0, %1, %2;" : "=r"(d) : "r"(a), "r"(b));
    return d;
}
__device__ __forceinline__ unsigned int cvt_bf16x2(float h_, float l_) {
    unsigned int r;
    asm("cvt.rn.bf16x2.f32 %0, %1, %2;" : "=r"(r) : "f"(h_), "f"(l_));
    return r;
}
__device__ __forceinline__ float bf_lo(unsigned int h) { return __uint_as_float(h << 16); }
__device__ __forceinline__ float bf_hi(unsigned int h) { return __uint_as_float(h & 0xFFFF0000u); }
__device__ __forceinline__ float ex2_approx(float x) {
    float r; asm("ex2.approx.f32 %0, %1;" : "=f"(r) : "f"(x)); return r;
}
__device__ __forceinline__ float lg2_approx(float x) {
    float r; asm("lg2.approx.f32 %0, %1;" : "=f"(r) : "f"(x)); return r;
}
__device__ __forceinline__ float rcp_approx(float x) {
    float r; asm("rcp.approx.f32 %0, %1;" : "=f"(r) : "f"(x)); return r;
}

#define LOG2E 1.4426950408889634f
#define LN2   0.6931471805599453

// One step for TWO independent batches (q = 0,1), interleaved for latency hiding.
// Free vars: u0[2],u1[2],r_pend[2],C2[2],s_v4,smkp[2],w,lane,E0,E1,FULL
#define CRF_STEP2(xqA_, xqB_, par_, ren_, cap_)                                  \
    do {                                                                         \
        int mkA = *smkp0++;                                                      \
        int mkB = *smkp1++;                                                      \
        float g0A, g1A, g0B, g1B, rinvA = 1.0f, rinvB = 1.0f;                    \
        if (ren_) {                                                              \
            float l2rA = lg2_approx(r_pend[0]);                                  \
            float l2rB = lg2_approx(r_pend[1]);                                  \
            rinvA = rcp_approx(r_pend[0]);                                       \
            rinvB = rcp_approx(r_pend[1]);                                       \
            g0A = ex2_approx(fmaf((xqA_).x, LOG2E, -l2rA));                      \
            g1A = ex2_approx(fmaf((xqA_).y, LOG2E, -l2rA));                      \
            g0B = ex2_approx(fmaf((xqB_).x, LOG2E, -l2rB));                      \
            g1B = ex2_approx(fmaf((xqB_).y, LOG2E, -l2rB));                      \
            C2[0] += l2rA;                                                       \
            C2[1] += l2rB;                                                       \
        } else {                                                                 \
            g0A = ex2_approx((xqA_).x * LOG2E);                                  \
            g1A = ex2_approx((xqA_).y * LOG2E);                                  \
            g0B = ex2_approx((xqB_).x * LOG2E);                                  \
            g1B = ex2_approx((xqB_).y * LOG2E);                                  \
        }                                                                        \
        const int buf_ = (par_) & 1;                                             \
        asm volatile("" ::: "memory");                                           \
        const uint4* vvA = (const uint4*)&s_v4[2 * w + 0][buf_][0];              \
        const uint4* vvB = (const uint4*)&s_v4[2 * w + 1][buf_][0];              \
        unsigned int a00A = 0u, a01A = 0u, a10A = 0u, a11A = 0u;                 \
        unsigned int a00B = 0u, a01B = 0u, a10B = 0u, a11B = 0u;                 \
        _Pragma("unroll")                                                        \
        for (int c = 0; c < 8; c++) {                                            \
            uint4 vpA = vvA[c];                                                  \
            uint4 vpB = vvB[c];                                                  \
            a00A = hfma2_bf(vpA.x, E0[4*c],   a00A);                             \
            a00B = hfma2_bf(vpB.x, E0[4*c],   a00B);                             \
            a10A = hfma2_bf(vpA.x, E1[4*c],   a10A);                             \
            a10B = hfma2_bf(vpB.x, E1[4*c],   a10B);                             \
            a01A = hfma2_bf(vpA.y, E0[4*c+1], a01A);                             \
            a01B = hfma2_bf(vpB.y, E0[4*c+1], a01B);                             \
            a11A = hfma2_bf(vpA.y, E1[4*c+1], a11A);                             \
            a11B = hfma2_bf(vpB.y, E1[4*c+1], a11B);                             \
            a00A = hfma2_bf(vpA.z, E0[4*c+2], a00A);                             \
            a00B = hfma2_bf(vpB.z, E0[4*c+2], a00B);                             \
            a10A = hfma2_bf(vpA.z, E1[4*c+2], a10A);                             \
            a10B = hfma2_bf(vpB.z, E1[4*c+2], a10B);                             \
            a01A = hfma2_bf(vpA.w, E0[4*c+3], a01A);                             \
            a01B = hfma2_bf(vpB.w, E0[4*c+3], a01B);                             \
            a11A = hfma2_bf(vpA.w, E1[4*c+3], a11A);                             \
            a11B = hfma2_bf(vpB.w, E1[4*c+3], a11B);                             \
        }                                                                        \
        unsigned int h0A = hadd2_bf(a00A, a01A);                                 \
        unsigned int h1A = hadd2_bf(a10A, a11A);                                 \
        unsigned int h0B = hadd2_bf(a00B, a01B);                                 \
        unsigned int h1B = hadd2_bf(a10B, a11B);                                 \
        float w0A = bf_lo(h0A) + bf_hi(h0A);                                     \
        float w1A = bf_lo(h1A) + bf_hi(h1A);                                     \
        float w0B = bf_lo(h0B) + bf_hi(h0B);                                     \
        float w1B = bf_lo(h1B) + bf_hi(h1B);                                     \
        float u0nA = w0A * g0A, u1nA = w1A * g1A;                                \
        float u0nB = w0B * g0B, u1nB = w1B * g1B;                                \
        float u0rA = (ren_) ? u0[0] * rinvA : u0[0];                             \
        float u1rA = (ren_) ? u1[0] * rinvA : u1[0];                             \
        float u0rB = (ren_) ? u0[1] * rinvB : u0[1];                             \
        float u1rB = (ren_) ? u1[1] * rinvB : u1[1];                             \
        u0[0] = mkA ? u0rA : u0nA;                                               \
        u1[0] = mkA ? u1rA : u1nA;                                               \
        u0[1] = mkB ? u0rB : u0nB;                                               \
        u1[1] = mkB ? u1rB : u1nB;                                               \
        asm volatile("" ::: "memory");                                           \
        ((unsigned int*)&s_v4[2 * w + 0][buf_ ^ 1][0])[lane] = cvt_bf16x2(u1[0], u0[0]); \
        ((unsigned int*)&s_v4[2 * w + 1][buf_ ^ 1][0])[lane] = cvt_bf16x2(u1[1], u0[1]); \
        if (cap_) {                                                              \
            r_pend[0] = __shfl_sync(FULL, u0[0], 0);                             \
            r_pend[1] = __shfl_sync(FULL, u0[1], 0);                             \
        }                                                                        \
    } while (0)

// ---------------- fused main: 2 batches per warp, 128 CTAs (1 per SM) ----------------
__global__ __launch_bounds__(128) void crf_main_kernel(
    const float* __restrict__ inputs,
    const float* __restrict__ trans,
    const unsigned char* __restrict__ masks,
    const int* __restrict__ tags,
    float* __restrict__ d_out, int out_size)
{
    __shared__ float s_trans[64 * 64];            // 16 KB
    __shared__ uint4 s_v4[8][2][8];               // per warp-batch slot, double-buffered
    __shared__ unsigned char s_mk[8][SS];         // per-batch masks
    __shared__ bool s_last;
    __shared__ double s_red[128];

    const int w    = threadIdx.x >> 5;
    const int lane = threadIdx.x & 31;
    const int bA   = blockIdx.x * 8 + 2 * w;      // batch A
    const int bB   = bA + 1;                      // batch B

    if (blockIdx.x == 0 && out_size >= 4097) {
        for (int i = threadIdx.x; i < 4096; i += 128) d_out[1 + i] = trans[i];
    }

    for (int i = threadIdx.x; i < 4096; i += 128) s_trans[i] = trans[i];
    for (int s = lane; s < SS; s += 32) {
        s_mk[2 * w + 0][s] = masks[bA * SS + s];
        s_mk[2 * w + 1][s] = masks[bB * SS + s];
    }
    __syncthreads();

    // E in bf16x2 registers, shared by both batches. lane owns outputs j0=2l, j1=2l+1.
    unsigned int E0[32], E1[32];
    {
        const int j0 = 2 * lane, j1 = 2 * lane + 1;
#pragma unroll
        for (int ii = 0; ii < 32; ii++) {
            float e0l = ex2_approx(s_trans[(2 * ii) * 64 + j0] * LOG2E);
            float e0h = ex2_approx(s_trans[(2 * ii + 1) * 64 + j0] * LOG2E);
            float e1l = ex2_approx(s_trans[(2 * ii) * 64 + j1] * LOG2E);
            float e1h = ex2_approx(s_trans[(2 * ii + 1) * 64 + j1] * LOG2E);
            E0[ii] = cvt_bf16x2(e0h, e0l);
            E1[ii] = cvt_bf16x2(e1h, e1l);
        }
    }

    const float* xbA = inputs + (size_t)bA * SS * TT;
    const float* xbB = inputs + (size_t)bB * SS * TT;
    const unsigned FULL = 0xFFFFFFFFu;

    // ---- path scores (independent of recursion) ----
    float pathA = 0.0f, pathB = 0.0f;
    for (int s0 = lane; s0 < SS; s0 += 32) {
        int tA = tags[bA * SS + s0];
        int tB = tags[bB * SS + s0];
        unsigned char mA = s_mk[2 * w + 0][s0];
        unsigned char mB = s_mk[2 * w + 1][s0];
        float termA = mA ? 0.0f : __ldg(&xbA[s0 * TT + tA]);
        float termB = mB ? 0.0f : __ldg(&xbB[s0 * TT + tB]);
        if (s0 > 0) {
            int tpA = tags[bA * SS + s0 - 1];
            int tpB = tags[bB * SS + s0 - 1];
            termA += mA ? 0.0f : s_trans[tpA * 64 + tA];
            termB += mB ? 0.0f : s_trans[tpB * 64 + tB];
        }
        pathA += termA;
        pathB += termB;
    }
#pragma unroll
    for (int off = 16; off > 0; off >>= 1) {
        pathA += __shfl_xor_sync(FULL, pathA, off);
        pathB += __shfl_xor_sync(FULL, pathB, off);
    }

    // ---- s = 0 init ----
    float2 xA0 = *(const float2*)(xbA + 2 * lane);
    float2 xB0 = *(const float2*)(xbB + 2 * lane);
    float c0[2];
    c0[0] = __shfl_sync(FULL, xA0.x, 0);
    c0[1] = __shfl_sync(FULL, xB0.x, 0);
    float C2[2] = {0.0f, 0.0f};
    float u0[2], u1[2];
    u0[0] = ex2_approx((xA0.x - c0[0]) * LOG2E);
    u1[0] = ex2_approx((xA0.y - c0[0]) * LOG2E);
    u0[1] = ex2_approx((xB0.x - c0[1]) * LOG2E);
    u1[1] = ex2_approx((xB0.y - c0[1]) * LOG2E);
    ((unsigned int*)&s_v4[2 * w + 0][1][0])[lane] = cvt_bf16x2(u1[0], u0[0]);
    ((unsigned int*)&s_v4[2 * w + 1][1][0])[lane] = cvt_bf16x2(u1[1], u0[1]);
    float r_pend[2] = {1.0f, 1.0f};

    // depth-8 prefetch queues
    float2 qA[8], qB[8];
#pragma unroll
    for (int u = 0; u < 8; u++) {
        qA[u] = *(const float2*)(xbA + (1 + u) * TT + 2 * lane);
        qB[u] = *(const float2*)(xbB + (1 + u) * TT + 2 * lane);
    }

    const unsigned char* smkp0 = &s_mk[2 * w + 0][1];
    const unsigned char* smkp1 = &s_mk[2 * w + 1][1];
    const float* xpfA  = xbA + 9 * TT;
    const float* xpfB  = xbB + 9 * TT;
    const float* xlimA = xbA + (SS - 1) * TT;
    const float* xlimB = xbB + (SS - 1) * TT;

    int s = 1;
    for (int it = 0; it < 63; it++, s += 8) {      // steps 1..504
#pragma unroll
        for (int u = 0; u < 8; u++) {
            float2 xqA = qA[u];
            float2 xqB = qB[u];
            const float* xrA = (xpfA < xlimA) ? xpfA : xlimA;
            const float* xrB = (xpfB < xlimB) ? xpfB : xlimB;
            qA[u] = *(const float2*)(xrA + 2 * lane);
            qB[u] = *(const float2*)(xrB + 2 * lane);
            xpfA += TT;
            xpfB += TT;
            CRF_STEP2(xqA, xqB, s + u,
                      (u == 0 || u == 4) ? 1 : 0,
                      (u == 2 || u == 6) ? 1 : 0);
        }
    }
    // epilogue: steps 505..511
#pragma unroll
    for (int u = 0; u < 7; u++) {
        float2 xqA = qA[u];
        float2 xqB = qB[u];
        CRF_STEP2(xqA, xqB, s + u,
                  (u == 0 || u == 4) ? 1 : 0,
                  (u == 2) ? 1 : 0);
    }

    // log_norm per batch
    float svA = u0[0] + u1[0];
    float svB = u0[1] + u1[1];
#pragma unroll
    for (int off = 16; off > 0; off >>= 1) {
        svA += __shfl_xor_sync(FULL, svA, off);
        svB += __shfl_xor_sync(FULL, svB, off);
    }
    if (lane == 0) {
        double lnA = (double)c0[0] + LN2 * ((double)C2[0] + (double)lg2_approx(svA));
        double lnB = (double)c0[1] + LN2 * ((double)C2[1] + (double)lg2_approx(svB));
        g_ll[bA] = (double)pathA - lnA;
        g_ll[bB] = (double)pathB - lnB;
    }

    // ---- last-block deterministic reduction ----
    __syncthreads();
    if (threadIdx.x == 0) {
        __threadfence();
        unsigned int old = atomicAdd(&g_ctr, 1u);
        s_last = (old == gridDim.x - 1);
    }
    __syncthreads();
    if (s_last) {
        int t = threadIdx.x;
        double acc = 0.0;
        for (int i = t; i < BB; i += 128) acc += g_ll[i];
        s_red[t] = acc;
        __syncthreads();
        for (int off = 64; off > 0; off >>= 1) {
            if (t < off) s_red[t] += s_red[t + off];
            __syncthreads();
        }
        if (t == 0) {
            d_out[0] = (float)(-s_red[0] / (double)BB);
            g_ctr = 0;
        }
    }
}

extern "C" void kernel_launch(void* const* d_in, const int* in_sizes, int n_in,
                              void* d_out, int out_size) {
    const float*         inputs = (const float*)d_in[0];
    const float*         trans  = (const float*)d_in[1];
    const unsigned char* masks  = (const unsigned char*)d_in[2];
    const int*           tags   = (const int*)d_in[3];
    float*               out    = (float*)d_out;

    crf_main_kernel<<<128, 128>>>(inputs, trans, masks, tags, out, out_size);
}